// round 17
// baseline (speedup 1.0000x reference)
#include <cuda_runtime.h>
#include <cuda_bf16.h>
#include <cstdint>

#define NN 50000
#define EE 800000
#define CC 128
#define NEG 0.01f

// Scratch (no allocation allowed -> __device__ globals)
__device__ float g_y[NN * CC];
__device__ float g_delta[NN * 3];
__device__ int   g_is64;
// CSR scratch
__device__ int g_deg[NN];
__device__ int g_off[NN];
__device__ int g_cur[NN];
__device__ int g_ssrc[EE];
__device__ int g_bsum[256];
// Fragment-major weights: per matrix 4096 x uint4 {bhi0,bhi1,blo0,blo1} = 64KB
// index (per matrix): ct*256 + kc*32 + g*4 + q
__device__ uint4 g_fragW[4 * 4096];

__device__ __forceinline__ float leaky(float v) {
    return v >= 0.0f ? v : NEG * v;
}

// ---------------------------------------------------------------------------
__global__ void detect_dtype_kernel(const int* __restrict__ ei32, int n_words)
{
    __shared__ int bad;
    if (threadIdx.x == 0) bad = 0;
    __syncthreads();
    int pairs = n_words / 2;
    for (int p = threadIdx.x; p < pairs; p += 256)
        if (ei32[2 * p + 1] != 0) bad = 1;
    __syncthreads();
    if (threadIdx.x == 0) g_is64 = bad ? 0 : 1;
}

// ---------------------------------------------------------------------------
__device__ __forceinline__ uint32_t pack_hi(float a, float b) {
    __nv_bfloat16 ha = __float2bfloat16(a), hb = __float2bfloat16(b);
    return (uint32_t)__bfloat16_as_ushort(ha) | ((uint32_t)__bfloat16_as_ushort(hb) << 16);
}
__device__ __forceinline__ uint32_t pack_lo(float a, float b) {
    __nv_bfloat16 ha = __float2bfloat16(a), hb = __float2bfloat16(b);
    __nv_bfloat16 la = __float2bfloat16(a - __bfloat162float(ha));
    __nv_bfloat16 lb = __float2bfloat16(b - __bfloat162float(hb));
    return (uint32_t)__bfloat16_as_ushort(la) | ((uint32_t)__bfloat16_as_ushort(lb) << 16);
}

__global__ void prep_weights_kernel(const float* __restrict__ w0,
                                    const float* __restrict__ w1,
                                    const float* __restrict__ w2,
                                    const float* __restrict__ w3)
{
    int idx = blockIdx.x * 256 + threadIdx.x;   // 4*4096 entries
    if (idx >= 4 * 4096) return;
    int m = idx >> 12;
    int rem = idx & 4095;
    int col = rem >> 5;        // 0..127
    int kc  = (rem >> 2) & 7;  // 0..7
    int q   = rem & 3;         // 0..3
    const float* w = (m == 0) ? w0 : (m == 1) ? w1 : (m == 2) ? w2 : w3;
    int k0 = kc * 16 + 2 * q;
    float a0 = w[(k0 + 0) * CC + col];
    float a1 = w[(k0 + 1) * CC + col];
    float a2 = w[(k0 + 8) * CC + col];
    float a3 = w[(k0 + 9) * CC + col];
    uint4 v;
    v.x = pack_hi(a0, a1);
    v.y = pack_hi(a2, a3);
    v.z = pack_lo(a0, a1);
    v.w = pack_lo(a2, a3);
    int ct = col >> 3, g = col & 7;
    g_fragW[m * 4096 + ct * 256 + kc * 32 + g * 4 + q] = v;
}

// ---------------------------------------------------------------------------
__device__ __forceinline__ void mma_bf16(float* c, const uint32_t* a, const uint32_t* b)
{
    asm volatile(
        "mma.sync.aligned.m16n8k16.row.col.f32.bf16.bf16.f32 "
        "{%0,%1,%2,%3}, {%4,%5,%6,%7}, {%8,%9}, {%0,%1,%2,%3};"
        : "+f"(c[0]), "+f"(c[1]), "+f"(c[2]), "+f"(c[3])
        : "r"(a[0]), "r"(a[1]), "r"(a[2]), "r"(a[3]), "r"(b[0]), "r"(b[1]));
}

__device__ __forceinline__ void cvt_hilo(float2 f, uint32_t& hi, uint32_t& lo)
{
    __nv_bfloat16 hx = __float2bfloat16(f.x);
    __nv_bfloat16 hy = __float2bfloat16(f.y);
    __nv_bfloat16 lx = __float2bfloat16(f.x - __bfloat162float(hx));
    __nv_bfloat16 ly = __float2bfloat16(f.y - __bfloat162float(hy));
    hi = (uint32_t)__bfloat16_as_ushort(hx) | ((uint32_t)__bfloat16_as_ushort(hy) << 16);
    lo = (uint32_t)__bfloat16_as_ushort(lx) | ((uint32_t)__bfloat16_as_ushort(ly) << 16);
}

// One kc-step of the inner loop given A-fragment source pointers.
__device__ __forceinline__ void inner_step(
    const float* a0p, const float* a1p, int k0,
    const uint4* wbase, int warp_n, float acc[8][4])
{
    float2 f00 = *(const float2*)(a0p + k0);
    float2 f10 = *(const float2*)(a1p + k0);
    float2 f01 = *(const float2*)(a0p + k0 + 8);
    float2 f11 = *(const float2*)(a1p + k0 + 8);
    uint32_t ahi[4], alo[4];
    cvt_hilo(f00, ahi[0], alo[0]);
    cvt_hilo(f10, ahi[1], alo[1]);
    cvt_hilo(f01, ahi[2], alo[2]);
    cvt_hilo(f11, ahi[3], alo[3]);
#pragma unroll
    for (int ct = 0; ct < 8; ct++) {
        uint4 wv = wbase[(warp_n * 8 + ct) * 256];
        uint32_t bh[2] = { wv.x, wv.y };
        uint32_t bl[2] = { wv.z, wv.w };
        mma_bf16(acc[ct], ahi, bh);
        mma_bf16(acc[ct], ahi, bl);
        mma_bf16(acc[ct], alo, bh);
    }
}

// ---------------------------------------------------------------------------
// Fused GEMM1+GEMM2 (R16, proven): x staged once (stride 136).
// Phase 1 (W=h_w1): delta = tanh(leaky(x@h_w1+h_b1) @ h_w2 + h_b2).
// Phase 2 (W=f_w'): y = x @ f_w[3:] + f_b.
// smem: x [0,69632); W [69632,135168); b1 +512; b2 +512; hw2 +1536.
// ---------------------------------------------------------------------------
#define F12_SW   69632
#define F12_B1   135168
#define F12_B2   135680
#define F12_HW2  136192
#define F12_TOT  137728

__global__ __launch_bounds__(512, 1) void gemm_fused12(
    const float* __restrict__ x,
    const uint4* __restrict__ fragW1, const uint4* __restrict__ fragW2,
    const float* __restrict__ b1v, const float* __restrict__ b2v,
    const float* __restrict__ hw2, const float* __restrict__ hb2,
    float* __restrict__ delta, float* __restrict__ yout, int M)
{
    extern __shared__ char sm[];
    float* sX = (float*)sm;                       // [128][136]
    uint4* sW = (uint4*)(sm + F12_SW);            // 4096 uint4
    const int tid = threadIdx.x;

#pragma unroll
    for (int i = 0; i < 8; i++)
        sW[tid + i * 512] = fragW1[tid + i * 512];
    if (tid < 128) {
        ((float*)(sm + F12_B1))[tid] = b1v[tid];
        ((float*)(sm + F12_B2))[tid] = b2v[tid];
    }
    for (int i = tid; i < 384; i += 512)
        ((float*)(sm + F12_HW2))[i] = hw2[i];

    // Stage full x tile [128 x 128] fp32, row stride 136
    {
        int srow = tid & 127;
        int segb = (tid >> 7) * 8;
        int grow = blockIdx.x * 128 + srow;
        const float4* src = (grow < M) ? (const float4*)(x + (size_t)grow * CC) : nullptr;
        float* dst = sX + srow * 136;
#pragma unroll
        for (int i = 0; i < 8; i++) {
            float4 v = src ? src[segb + i] : make_float4(0.f, 0.f, 0.f, 0.f);
            *(float4*)(dst + (segb + i) * 4) = v;
        }
    }
    __syncthreads();

    const int warp = tid >> 5, lane = tid & 31;
    const int g = lane >> 2, q = lane & 3;
    const int warp_m = warp >> 1, warp_n = warp & 1;
    const int r0 = warp_m * 16;
    const float* a0base = sX + (r0 + g) * 136;
    const float* a1base = sX + (r0 + g + 8) * 136;

    float acc[8][4];
#pragma unroll
    for (int ct = 0; ct < 8; ct++)
#pragma unroll
        for (int c = 0; c < 4; c++) acc[ct][c] = 0.f;

    // ---- phase 1: hidden = x @ h_w1 ----
#pragma unroll
    for (int kc = 0; kc < 8; kc++)
        inner_step(a0base, a1base, kc * 16 + q * 2,
                   sW + kc * 32 + g * 4 + q, warp_n, acc);
    __syncthreads();

    // delta epilogue
    {
        const float* sb1 = (const float*)(sm + F12_B1);
        const float* shw2 = (const float*)(sm + F12_HW2);
        float* sPart = (float*)(sm + F12_SW);     // [2][128][3] (W1 dead)
        float p0[3] = {0.f, 0.f, 0.f}, p1[3] = {0.f, 0.f, 0.f};
#pragma unroll
        for (int ct = 0; ct < 8; ct++) {
            int col = (warp_n * 8 + ct) * 8 + q * 2;
            float b0 = sb1[col], b1 = sb1[col + 1];
            float v00 = leaky(acc[ct][0] + b0), v01 = leaky(acc[ct][1] + b1);
            float v10 = leaky(acc[ct][2] + b0), v11 = leaky(acc[ct][3] + b1);
#pragma unroll
            for (int d = 0; d < 3; d++) {
                p0[d] += v00 * shw2[col * 3 + d] + v01 * shw2[(col + 1) * 3 + d];
                p1[d] += v10 * shw2[col * 3 + d] + v11 * shw2[(col + 1) * 3 + d];
            }
        }
#pragma unroll
        for (int d = 0; d < 3; d++) {
            p0[d] += __shfl_xor_sync(0xFFFFFFFFu, p0[d], 1);
            p0[d] += __shfl_xor_sync(0xFFFFFFFFu, p0[d], 2);
            p1[d] += __shfl_xor_sync(0xFFFFFFFFu, p1[d], 1);
            p1[d] += __shfl_xor_sync(0xFFFFFFFFu, p1[d], 2);
        }
        if (q == 0) {
            int row0 = r0 + g, row1 = row0 + 8;
#pragma unroll
            for (int d = 0; d < 3; d++) {
                sPart[(warp_n * 128 + row0) * 3 + d] = p0[d];
                sPart[(warp_n * 128 + row1) * 3 + d] = p1[d];
            }
        }
        __syncthreads();
        if (tid < 128) {
            int orow = blockIdx.x * 128 + tid;
            if (orow < M) {
#pragma unroll
                for (int d = 0; d < 3; d++)
                    delta[orow * 3 + d] = tanhf(sPart[tid * 3 + d] +
                                                sPart[(128 + tid) * 3 + d] + hb2[d]);
            }
        }
    }
    __syncthreads();

    // swap weights to W2 (f_w'), zero accumulators
#pragma unroll
    for (int i = 0; i < 8; i++)
        sW[tid + i * 512] = fragW2[tid + i * 512];
#pragma unroll
    for (int ct = 0; ct < 8; ct++)
#pragma unroll
        for (int c = 0; c < 4; c++) acc[ct][c] = 0.f;
    __syncthreads();

    // ---- phase 2: y = x @ f_w' + f_b ----
#pragma unroll
    for (int kc = 0; kc < 8; kc++)
        inner_step(a0base, a1base, kc * 16 + q * 2,
                   sW + kc * 32 + g * 4 + q, warp_n, acc);

    {
        const float* sb2 = (const float*)(sm + F12_B2);
        int orow0 = blockIdx.x * 128 + r0 + g;
        int orow1 = orow0 + 8;
#pragma unroll
        for (int ct = 0; ct < 8; ct++) {
            int col = (warp_n * 8 + ct) * 8 + q * 2;
            float b0 = sb2[col], b1 = sb2[col + 1];
            if (orow0 < M)
                *(float2*)(yout + (size_t)orow0 * CC + col) =
                    make_float2(acc[ct][0] + b0, acc[ct][1] + b1);
            if (orow1 < M)
                *(float2*)(yout + (size_t)orow1 * CC + col) =
                    make_float2(acc[ct][2] + b0, acc[ct][3] + b1);
        }
    }
}

// ---------------------------------------------------------------------------
// Fused AGGR+GEMM3+GEMM4: phase 0 computes aggr rows [blk*128, +128) in smem
// (warp-per-node gather over CSR, identical math/order to the old standalone
// aggregate_kernel), then out = leaky(aggr@W1 + b1) @ W2 + b2 + x.
// smem: aggr [0,69632) stride 136; t [69632,137216) stride 132;
//       W [137216,202752); b1 +512; b2 +512.  203776 B, 1 CTA/SM.
// ---------------------------------------------------------------------------
#define FA_ST   69632
#define FA_SW   137216
#define FA_B1   202752
#define FA_B2   203264
#define FA_TOT  203776

__global__ __launch_bounds__(512, 1) void gemm_fused034(
    const int* __restrict__ off, const int* __restrict__ deg,
    const int* __restrict__ ssrc, const float* __restrict__ pos,
    const float* __restrict__ delta, const float* __restrict__ y,
    const float* __restrict__ f_w,
    const uint4* __restrict__ fragW1, const uint4* __restrict__ fragW2,
    const float* __restrict__ b1v, const float* __restrict__ b2v,
    const float* __restrict__ resid, float* __restrict__ out, int M)
{
    extern __shared__ char sm[];
    float* sA = (float*)sm;                       // [128][136] aggr
    float* sT = (float*)(sm + FA_ST);             // [128][132] t
    uint4* sW = (uint4*)(sm + FA_SW);             // 4096 uint4
    const int tid = threadIdx.x;

#pragma unroll
    for (int i = 0; i < 8; i++)
        sW[tid + i * 512] = fragW1[tid + i * 512];
    if (tid < 128) {
        ((float*)(sm + FA_B1))[tid] = b1v[tid];
        ((float*)(sm + FA_B2))[tid] = b2v[tid];
    }

    const int warp = tid >> 5, lane = tid & 31;

    // ---- phase 0: aggregate 8 nodes per warp into sA ----
    {
        int c = lane * 4;
        float4 w0 = *(const float4*)(f_w + 0 * CC + c);
        float4 w1 = *(const float4*)(f_w + 1 * CC + c);
        float4 w2 = *(const float4*)(f_w + 2 * CC + c);
#pragma unroll
        for (int i = 0; i < 8; i++) {
            int row = warp * 8 + i;
            int node = blockIdx.x * 128 + row;
            float4 acc4 = make_float4(0.f, 0.f, 0.f, 0.f);
            if (node < M) {
                float b0 = delta[node * 3 + 0] - pos[node * 3 + 0];
                float b1 = delta[node * 3 + 1] - pos[node * 3 + 1];
                float b2 = delta[node * 3 + 2] - pos[node * 3 + 2];
                int s = off[node], n = deg[node];
                int e = 0;
                for (; e + 2 <= n; e += 2) {
                    int ja = __ldg(&ssrc[s + e]);
                    int jb = __ldg(&ssrc[s + e + 1]);
                    float ra0 = __ldg(&pos[ja * 3 + 0]) + b0;
                    float ra1 = __ldg(&pos[ja * 3 + 1]) + b1;
                    float ra2 = __ldg(&pos[ja * 3 + 2]) + b2;
                    float rb0 = __ldg(&pos[jb * 3 + 0]) + b0;
                    float rb1 = __ldg(&pos[jb * 3 + 1]) + b1;
                    float rb2 = __ldg(&pos[jb * 3 + 2]) + b2;
                    float4 ya = *(const float4*)(y + (size_t)ja * CC + c);
                    float4 yb = *(const float4*)(y + (size_t)jb * CC + c);
                    acc4.x += leaky(ya.x + ra0 * w0.x + ra1 * w1.x + ra2 * w2.x)
                            + leaky(yb.x + rb0 * w0.x + rb1 * w1.x + rb2 * w2.x);
                    acc4.y += leaky(ya.y + ra0 * w0.y + ra1 * w1.y + ra2 * w2.y)
                            + leaky(yb.y + rb0 * w0.y + rb1 * w1.y + rb2 * w2.y);
                    acc4.z += leaky(ya.z + ra0 * w0.z + ra1 * w1.z + ra2 * w2.z)
                            + leaky(yb.z + rb0 * w0.z + rb1 * w1.z + rb2 * w2.z);
                    acc4.w += leaky(ya.w + ra0 * w0.w + ra1 * w1.w + ra2 * w2.w)
                            + leaky(yb.w + rb0 * w0.w + rb1 * w1.w + rb2 * w2.w);
                }
                for (; e < n; e++) {
                    int j = __ldg(&ssrc[s + e]);
                    float r0 = __ldg(&pos[j * 3 + 0]) + b0;
                    float r1 = __ldg(&pos[j * 3 + 1]) + b1;
                    float r2 = __ldg(&pos[j * 3 + 2]) + b2;
                    float4 yv = *(const float4*)(y + (size_t)j * CC + c);
                    acc4.x += leaky(yv.x + r0 * w0.x + r1 * w1.x + r2 * w2.x);
                    acc4.y += leaky(yv.y + r0 * w0.y + r1 * w1.y + r2 * w2.y);
                    acc4.z += leaky(yv.z + r0 * w0.z + r1 * w1.z + r2 * w2.z);
                    acc4.w += leaky(yv.w + r0 * w0.w + r1 * w1.w + r2 * w2.w);
                }
            }
            *(float4*)(sA + row * 136 + c) = acc4;
        }
    }
    __syncthreads();

    const int g = lane >> 2, q = lane & 3;
    const int warp_m = warp >> 1, warp_n = warp & 1;
    const int r0 = warp_m * 16;
    const float* a0base = sA + (r0 + g) * 136;
    const float* a1base = sA + (r0 + g + 8) * 136;

    float acc[8][4];
#pragma unroll
    for (int ct = 0; ct < 8; ct++)
#pragma unroll
        for (int c = 0; c < 4; c++) acc[ct][c] = 0.f;

    // ---- phase 1: t = aggr @ W1 ----
#pragma unroll
    for (int kc = 0; kc < 8; kc++)
        inner_step(a0base, a1base, kc * 16 + q * 2,
                   sW + kc * 32 + g * 4 + q, warp_n, acc);

    // epilogue 1: leaky(acc + b1) -> sT
    {
        const float* sb1 = (const float*)(sm + FA_B1);
        int row0 = r0 + g, row1 = row0 + 8;
#pragma unroll
        for (int ct = 0; ct < 8; ct++) {
            int col = (warp_n * 8 + ct) * 8 + q * 2;
            float b0 = sb1[col], b1 = sb1[col + 1];
            *(float2*)(sT + row0 * 132 + col) =
                make_float2(leaky(acc[ct][0] + b0), leaky(acc[ct][1] + b1));
            *(float2*)(sT + row1 * 132 + col) =
                make_float2(leaky(acc[ct][2] + b0), leaky(acc[ct][3] + b1));
        }
    }
    __syncthreads();

    // swap weights to W2
#pragma unroll
    for (int i = 0; i < 8; i++)
        sW[tid + i * 512] = fragW2[tid + i * 512];
#pragma unroll
    for (int ct = 0; ct < 8; ct++)
#pragma unroll
        for (int c = 0; c < 4; c++) acc[ct][c] = 0.f;
    __syncthreads();

    // ---- phase 2: out = t @ W2 + b2 + x ----
    {
        const float* t0base = sT + (r0 + g) * 132;
        const float* t1base = sT + (r0 + g + 8) * 132;
#pragma unroll
        for (int kc = 0; kc < 8; kc++)
            inner_step(t0base, t1base, kc * 16 + q * 2,
                       sW + kc * 32 + g * 4 + q, warp_n, acc);
    }

    {
        const float* sb2 = (const float*)(sm + FA_B2);
        int orow0 = blockIdx.x * 128 + r0 + g;
        int orow1 = orow0 + 8;
#pragma unroll
        for (int ct = 0; ct < 8; ct++) {
            int col = (warp_n * 8 + ct) * 8 + q * 2;
            float b0 = sb2[col], b1 = sb2[col + 1];
            if (orow0 < M) {
                float2 r = *(const float2*)(resid + (size_t)orow0 * CC + col);
                *(float2*)(out + (size_t)orow0 * CC + col) =
                    make_float2(acc[ct][0] + b0 + r.x, acc[ct][1] + b1 + r.y);
            }
            if (orow1 < M) {
                float2 r = *(const float2*)(resid + (size_t)orow1 * CC + col);
                *(float2*)(out + (size_t)orow1 * CC + col) =
                    make_float2(acc[ct][2] + b0 + r.x, acc[ct][3] + b1 + r.y);
            }
        }
    }
}

// ======================= CSR build =========================================
__global__ void zero_int_kernel(int* __restrict__ p, int n)
{
    int i = blockIdx.x * 256 + threadIdx.x;
    if (i < n) p[i] = 0;
}

__global__ void hist_kernel(const void* __restrict__ ei_raw, int* __restrict__ deg,
                            int E, int M)
{
    int base = (blockIdx.x * 256 + threadIdx.x) * 4;
    if (base >= E) return;
    int is64 = g_is64;
    const long long* e64 = (const long long*)ei_raw;
    const int* e32 = (const int*)ei_raw;
    int idx[4];
#pragma unroll
    for (int k = 0; k < 4; k++) {
        int e = base + k;
        idx[k] = (e < E) ? (is64 ? (int)e64[E + e] : e32[E + e]) : -1;
    }
#pragma unroll
    for (int k = 0; k < 4; k++)
        if ((unsigned)idx[k] < (unsigned)M) atomicAdd(&deg[idx[k]], 1);
}

__global__ void scan1_kernel(const int* __restrict__ deg, int* __restrict__ off,
                             int* __restrict__ bsum, int M)
{
    __shared__ int s[256];
    int tid = threadIdx.x;
    int i = blockIdx.x * 256 + tid;
    int d = (i < M) ? deg[i] : 0;
    s[tid] = d;
    __syncthreads();
#pragma unroll
    for (int o = 1; o < 256; o <<= 1) {
        int t = (tid >= o) ? s[tid - o] : 0;
        __syncthreads();
        s[tid] += t;
        __syncthreads();
    }
    if (i < M) off[i] = s[tid] - d;
    if (tid == 255) bsum[blockIdx.x] = s[255];
}

__global__ void scan2_kernel(int* __restrict__ bsum, int nb)
{
    __shared__ int s[256];
    int tid = threadIdx.x;
    int d = (tid < nb) ? bsum[tid] : 0;
    s[tid] = d;
    __syncthreads();
#pragma unroll
    for (int o = 1; o < 256; o <<= 1) {
        int t = (tid >= o) ? s[tid - o] : 0;
        __syncthreads();
        s[tid] += t;
        __syncthreads();
    }
    if (tid < nb) bsum[tid] = s[tid] - d;
}

__global__ void scan3_kernel(int* __restrict__ off, int* __restrict__ cur,
                             const int* __restrict__ bsum, int M)
{
    int i = blockIdx.x * 256 + threadIdx.x;
    if (i >= M) return;
    int v = off[i] + bsum[blockIdx.x];
    off[i] = v;
    cur[i] = v;
}

__global__ void scatter_kernel(const void* __restrict__ ei_raw,
                               int* __restrict__ cur, int* __restrict__ ssrc,
                               int E, int M)
{
    int base = (blockIdx.x * 256 + threadIdx.x) * 4;
    if (base >= E) return;
    int is64 = g_is64;
    const long long* e64 = (const long long*)ei_raw;
    const int* e32 = (const int*)ei_raw;
    int js[4], is_[4];
#pragma unroll
    for (int k = 0; k < 4; k++) {
        int e = base + k;
        if (e < E) {
            js[k]  = is64 ? (int)e64[e]     : e32[e];
            is_[k] = is64 ? (int)e64[E + e] : e32[E + e];
        } else {
            js[k] = -1; is_[k] = -1;
        }
    }
#pragma unroll
    for (int k = 0; k < 4; k++) {
        if ((unsigned)js[k] < (unsigned)M && (unsigned)is_[k] < (unsigned)M) {
            int pos = atomicAdd(&cur[is_[k]], 1);
            ssrc[pos] = js[k];
        }
    }
}

// ---------------------------------------------------------------------------
extern "C" void kernel_launch(void* const* d_in, const int* in_sizes, int n_in,
                              void* d_out, int out_size)
{
    const float* x      = (const float*)d_in[0];
    const float* pos    = (const float*)d_in[1];
    const void*  ei     = d_in[2];
    const float* h_w1   = (const float*)d_in[3];
    const float* h_b1   = (const float*)d_in[4];
    const float* h_w2   = (const float*)d_in[5];
    const float* h_b2   = (const float*)d_in[6];
    const float* f_w    = (const float*)d_in[7];
    const float* f_b    = (const float*)d_in[8];
    const float* g_w1   = (const float*)d_in[9];
    const float* g_b1   = (const float*)d_in[10];
    const float* g_w2   = (const float*)d_in[11];
    const float* g_b2   = (const float*)d_in[12];
    float* out = (float*)d_out;

    const int M = in_sizes[0] / CC;  // 50000
    const int E = in_sizes[2] / 2;   // 800000

    float *y, *delta;
    int *deg, *off, *cur, *ssrc, *bsum;
    uint4* fragW;
    cudaGetSymbolAddress((void**)&y,     g_y);
    cudaGetSymbolAddress((void**)&delta, g_delta);
    cudaGetSymbolAddress((void**)&deg,   g_deg);
    cudaGetSymbolAddress((void**)&off,   g_off);
    cudaGetSymbolAddress((void**)&cur,   g_cur);
    cudaGetSymbolAddress((void**)&ssrc,  g_ssrc);
    cudaGetSymbolAddress((void**)&bsum,  g_bsum);
    cudaGetSymbolAddress((void**)&fragW, g_fragW);

    static int inited = 0;
    static cudaStream_t sB = nullptr;
    static cudaEvent_t evFork = nullptr, evJoin = nullptr;
    if (!inited) {
        cudaFuncSetAttribute(gemm_fused12, cudaFuncAttributeMaxDynamicSharedMemorySize, F12_TOT);
        cudaFuncSetAttribute(gemm_fused034, cudaFuncAttributeMaxDynamicSharedMemorySize, FA_TOT);
        cudaStreamCreateWithFlags(&sB, cudaStreamNonBlocking);
        cudaEventCreateWithFlags(&evFork, cudaEventDisableTiming);
        cudaEventCreateWithFlags(&evJoin, cudaEventDisableTiming);
        inited = 1;
    }

    const int gcta = (M + 127) / 128;
    const int ncta = (M + 255) / 256;
    const int e4cta = (E + 1023) / 1024;

    // --- stream 0: dtype detect ---
    detect_dtype_kernel<<<1, 256>>>((const int*)ei, 2048);
    cudaEventRecord(evFork, 0);

    // branch B (sB): CSR build (hidden under fused12)
    cudaStreamWaitEvent(sB, evFork, 0);
    zero_int_kernel<<<ncta, 256, 0, sB>>>(deg, M);
    hist_kernel<<<e4cta, 256, 0, sB>>>(ei, deg, E, M);
    scan1_kernel<<<ncta, 256, 0, sB>>>(deg, off, bsum, M);
    scan2_kernel<<<1, 256, 0, sB>>>(bsum, ncta);
    scan3_kernel<<<ncta, 256, 0, sB>>>(off, cur, bsum, M);
    scatter_kernel<<<e4cta, 256, 0, sB>>>(ei, cur, ssrc, E, M);
    cudaEventRecord(evJoin, sB);

    // stream 0: weight prep + fused GEMM1+GEMM2
    prep_weights_kernel<<<(4 * 4096 + 255) / 256, 256>>>(h_w1, f_w + 3 * CC, g_w1, g_w2);
    gemm_fused12<<<gcta, 512, F12_TOT>>>(x, fragW + 0 * 4096, fragW + 1 * 4096,
                                         h_b1, f_b, h_w2, h_b2, delta, y, M);

    // --- join: fused aggr+GEMM3+GEMM4 needs CSR + delta + y ---
    cudaStreamWaitEvent(0, evJoin, 0);
    gemm_fused034<<<gcta, 512, FA_TOT>>>(off, deg, ssrc, pos, delta, y, f_w,
                                         fragW + 2 * 4096, fragW + 3 * 4096,
                                         g_b1, g_b2, x, out, M);
}